// round 6
// baseline (speedup 1.0000x reference)
#include <cuda_runtime.h>

typedef unsigned long long u64;

// ---------- f32x2 packed helpers (sm_100+) ----------
static __device__ __forceinline__ u64 pk2(float lo, float hi) {
    u64 r; asm("mov.b64 %0, {%1, %2};" : "=l"(r) : "f"(lo), "f"(hi)); return r;
}
static __device__ __forceinline__ void upk2(u64 v, float& lo, float& hi) {
    asm("mov.b64 {%0, %1}, %2;" : "=f"(lo), "=f"(hi) : "l"(v));
}
static __device__ __forceinline__ u64 ffma2(u64 a, u64 b, u64 c) {
    u64 d; asm("fma.rn.f32x2 %0, %1, %2, %3;" : "=l"(d) : "l"(a), "l"(b), "l"(c)); return d;
}

static __device__ __forceinline__ float softplus_fast(float v) {
    return fmaxf(v, 0.0f) + __logf(1.0f + __expf(-fabsf(v)));
}

#define C_HALF_P 0.505f
#define C_HALF_M 0.495f
#define ROWS_PER_THREAD 2
#define TPB 256
#define ROWS_PER_BLOCK (TPB * ROWS_PER_THREAD)

// Packed per-jp weights: w[jp*8 + q]
//   q=0..3 : (W1[2jp][q], W1[2jp+1][q])
//   q=4    : (b1[2jp],   b1[2jp+1])
//   q=5..7 : 0.495*(V_m[2jp], V_m[2jp+1]), m=q-5
struct ConstsPack {
    u64   w[256];
    float M[12];   // 0.505*(V_m W1)[k]  (m*4+k)
    float C[3];    // bias_m + 0.505*(V_m . b1)
    float pad;
};

__device__ ConstsPack g_scratch;
__constant__ ConstsPack g_c;

// ---- prep kernel: build packed weights into device scratch ----
__global__ void dln_prep(const float* __restrict__ W1, const float* __restrict__ b1,
                         const float* __restrict__ Wd, const float* __restrict__ bd,
                         const float* __restrict__ Wo, const float* __restrict__ bo)
{
    const int t = threadIdx.x;
    {
        int jp = t >> 3, q = t & 7;
        int j0 = 2 * jp, j1 = j0 + 1;
        float lo, hi;
        if (q < 4) {
            lo = W1[j0 * 4 + q]; hi = W1[j1 * 4 + q];
        } else if (q == 4) {
            lo = b1[j0]; hi = b1[j1];
        } else {
            int m = q - 5;
            const float* Vm = (m < 2) ? (Wd + m * 64) : Wo;
            lo = C_HALF_M * Vm[j0]; hi = C_HALF_M * Vm[j1];
        }
        g_scratch.w[t] = pk2(lo, hi);
    }
    if (t < 12) {
        int m = t >> 2, k = t & 3;
        const float* Vm = (m == 0) ? Wd : ((m == 1) ? (Wd + 64) : Wo);
        float s = 0.0f;
        #pragma unroll 8
        for (int j = 0; j < 64; ++j) s = fmaf(Vm[j], W1[j * 4 + k], s);
        g_scratch.M[t] = C_HALF_P * s;
    }
    if (t >= 12 && t < 15) {
        int m = t - 12;
        const float* Vm = (m == 0) ? Wd : ((m == 1) ? (Wd + 64) : Wo);
        float s = 0.0f;
        #pragma unroll 8
        for (int j = 0; j < 64; ++j) s = fmaf(Vm[j], b1[j], s);
        float bias = (m == 0) ? bd[0] : ((m == 1) ? bd[1] : bo[0]);
        g_scratch.C[m] = bias + C_HALF_P * s;
    }
}

// ---- main kernel: weights from __constant__ (uniform-const port / UR path) ----
__global__ __launch_bounds__(TPB, 6)
void dln_kernel(const float* __restrict__ x, float* __restrict__ out, int n)
{
    const int t = threadIdx.x;
    const int rowBase = blockIdx.x * ROWS_PER_BLOCK + t;   // coalesced: +i*TPB
    const float4* x4 = reinterpret_cast<const float4*>(x);
    float4* o4 = reinterpret_cast<float4*>(out);
    const u64 ABSM = 0x7fffffff7fffffffULL;

    u64 X[ROWS_PER_THREAD][4];
    #pragma unroll
    for (int i = 0; i < ROWS_PER_THREAD; ++i) {
        int r = rowBase + i * TPB;
        float4 v = (r < n) ? x4[r] : make_float4(0.f, 0.f, 0.f, 0.f);
        X[i][0] = pk2(v.x, v.x);
        X[i][1] = pk2(v.y, v.y);
        X[i][2] = pk2(v.z, v.z);
        X[i][3] = pk2(v.w, v.w);
    }

    u64 S0[ROWS_PER_THREAD], S1[ROWS_PER_THREAD], S2[ROWS_PER_THREAD];
    #pragma unroll
    for (int i = 0; i < ROWS_PER_THREAD; ++i) { S0[i] = 0ull; S1[i] = 0ull; S2[i] = 0ull; }

    #pragma unroll
    for (int jp = 0; jp < 32; ++jp) {
        const u64 wk0 = g_c.w[jp * 8 + 0];
        const u64 wk1 = g_c.w[jp * 8 + 1];
        const u64 wk2 = g_c.w[jp * 8 + 2];
        const u64 wk3 = g_c.w[jp * 8 + 3];
        const u64 bb  = g_c.w[jp * 8 + 4];
        const u64 v0  = g_c.w[jp * 8 + 5];
        const u64 v1  = g_c.w[jp * 8 + 6];
        const u64 v2  = g_c.w[jp * 8 + 7];

        #pragma unroll
        for (int i = 0; i < ROWS_PER_THREAD; ++i) {
            u64 a = bb;
            a = ffma2(wk0, X[i][0], a);
            a = ffma2(wk1, X[i][1], a);
            a = ffma2(wk2, X[i][2], a);
            a = ffma2(wk3, X[i][3], a);
            a &= ABSM;                           // packed |a|
            S0[i] = ffma2(v0, a, S0[i]);
            S1[i] = ffma2(v1, a, S1[i]);
            S2[i] = ffma2(v2, a, S2[i]);
        }
    }

    const float m0 = g_c.M[0], m1 = g_c.M[1], m2  = g_c.M[2],  m3  = g_c.M[3];
    const float m4 = g_c.M[4], m5 = g_c.M[5], m6  = g_c.M[6],  m7  = g_c.M[7];
    const float m8 = g_c.M[8], m9 = g_c.M[9], m10 = g_c.M[10], m11 = g_c.M[11];
    const float c0 = g_c.C[0], c1 = g_c.C[1], c2  = g_c.C[2];

    #pragma unroll
    for (int i = 0; i < ROWS_PER_THREAD; ++i) {
        int r = rowBase + i * TPB;
        if (r >= n) continue;
        float lo_, hi_;
        upk2(S0[i], lo_, hi_); float s0 = lo_ + hi_;
        upk2(S1[i], lo_, hi_); float s1 = lo_ + hi_;
        upk2(S2[i], lo_, hi_); float s2 = lo_ + hi_;

        float xk0, xk1, xk2, xk3, junk;
        upk2(X[i][0], xk0, junk);
        upk2(X[i][1], xk1, junk);
        upk2(X[i][2], xk2, junk);
        upk2(X[i][3], xk3, junk);

        float z0 = fmaf(m3,  xk3, fmaf(m2,  xk2, fmaf(m1, xk1, fmaf(m0, xk0, c0)))) + s0;
        float z1 = fmaf(m7,  xk3, fmaf(m6,  xk2, fmaf(m5, xk1, fmaf(m4, xk0, c1)))) + s1;
        float z2 = fmaf(m11, xk3, fmaf(m10, xk2, fmaf(m9, xk1, fmaf(m8, xk0, c2)))) + s2;

        float d0 = softplus_fast(z0);
        float d1 = softplus_fast(z1);
        float l  = z2;
        float4 o;
        o.x = fmaf(d0, d0, 1e-9f);
        o.y = d0 * l;
        o.z = o.y;
        o.w = fmaf(l, l, fmaf(d1, d1, 1e-9f));
        o4[r] = o;
    }
}

extern "C" void kernel_launch(void* const* d_in, const int* in_sizes, int n_in,
                              void* d_out, int out_size)
{
    const float* x  = (const float*)d_in[0];
    const float* W1 = (const float*)d_in[1];
    const float* b1 = (const float*)d_in[2];
    const float* Wd = (const float*)d_in[3];
    const float* bd = (const float*)d_in[4];
    const float* Wo = (const float*)d_in[5];
    const float* bo = (const float*)d_in[6];
    float* out = (float*)d_out;

    int n = in_sizes[0] / 4;                       // rows
    int blocks = (n + ROWS_PER_BLOCK - 1) / ROWS_PER_BLOCK;

    // 1) build packed weights in device scratch
    dln_prep<<<1, 256>>>(W1, b1, Wd, bd, Wo, bo);

    // 2) D2D copy scratch -> __constant__ (graph-capturable memcpy node)
    void* src = nullptr;
    cudaGetSymbolAddress(&src, g_scratch);
    cudaMemcpyToSymbolAsync(g_c, src, sizeof(ConstsPack), 0,
                            cudaMemcpyDeviceToDevice, 0);

    // 3) main kernel
    dln_kernel<<<blocks, TPB>>>(x, out, n);
}